// round 7
// baseline (speedup 1.0000x reference)
#include <cuda_runtime.h>
#include <cuda_fp16.h>
#include <cstdint>
#include <math.h>

// Problem constants
#define B_   16
#define CIN  64
#define COUT 64
#define H_   128
#define W_   128
#define HW   (H_*W_)          // 16384
#define NPIX (B_*COUT*HW)     // 16,777,216

#define XPAD 72               // halves per px row (144 B): ldmatrix rows 16B-aligned
#define WPAD 72
#define XROW (132 * XPAD)     // halves per staged input row

// ---------------- device scratch (static, no allocation) ----------------
__device__ __align__(16) __half g_wh[25 * 64 * WPAD];   // [khw][cout][WPAD]
__device__ float g_dog[25];
__device__ __align__(16) float g_ybuf[NPIX];

__device__ __forceinline__ int refl(int i) {
    if (i < 0) return -i;
    if (i > 127) return 254 - i;
    return i;
}

__device__ __forceinline__ uint32_t smem_u32(const void* p) {
    uint32_t a;
    asm("{ .reg .u64 t; cvta.to.shared.u64 t, %1; cvt.u32.u64 %0, t; }"
        : "=r"(a) : "l"(p));
    return a;
}

// ---------------- kernel 1: weight prep (one block per cout) ----------------
__global__ __launch_bounds__(128)
void prep_kernel(const float* __restrict__ w) {
    __shared__ float ws[1600];
    __shared__ float invn[25];
    const int tid = threadIdx.x;
    const int o = blockIdx.x;

    for (int i = tid; i < 1600; i += 128) ws[i] = w[o * 1600 + i];
    __syncthreads();
    if (tid < 25) {
        float s = 0.f;
        #pragma unroll 8
        for (int ci = 0; ci < CIN; ci++) {
            float v = ws[ci * 25 + tid];
            s += v * v;
        }
        invn[tid] = 1.f / fmaxf(sqrtf(s), 1e-12f);
    }
    __syncthreads();
    for (int i = tid; i < 1600; i += 128) {
        int khw = i >> 6, ci = i & 63;
        float v = fabsf(ws[ci * 25 + khw]) * invn[khw];
        g_wh[(size_t)(khw * 64 + o) * WPAD + ci] = __float2half(v);
    }
    if (o == 0 && tid < 25) {
        int u = tid / 5 - 2, v = tid % 5 - 2;
        float d2 = (float)(u * u + v * v);
        const float two_pi = 6.2831853071795864769f;
        const float ae = 1.f / (two_pi * 1.44f);   // sigma_e = 1.2
        const float ai = 1.f / (two_pi * 1.96f);   // sigma_i = 1.4
        float val = ae * expf(-d2 / (2.f * 1.44f)) - ai * expf(-d2 / (2.f * 1.96f));
        g_dog[tid] = val / (ae - ai);
    }
}

// ---------------- kernel 2: fp16 HMMA implicit-GEMM conv + cosine ----------------
// Grid (64, 16): CTA = 2 output y-rows x 128 px x 64 cout. 512 thr = 16 warps.
// Warp w: yrow g = w>>3, px block px0 = (w&7)*16. Warp tile M16 x N64.
// smem: Ws[5kw][64][WPAD] 46080 | Xs[6 rows][132 px][XPAD] 114048 | Crow[6*132] | Ssum[2*132]
#define WS_BYTES (5 * 64 * WPAD * 2)            // 46080
#define XS_BYTES (6 * 132 * XPAD * 2)           // 114048
#define CROW_FLOATS (6 * 132)
#define SSUM_FLOATS (2 * 132)
#define DSMEM (WS_BYTES + XS_BYTES + (CROW_FLOATS + SSUM_FLOATS) * 4)  // 168480

__global__ __launch_bounds__(512, 1)
void main_mma_kernel(const float* __restrict__ x) {
    extern __shared__ char dsm[];
    __half* Ws   = (__half*)dsm;
    __half* Xs   = (__half*)(dsm + WS_BYTES);
    float*  Crow = (float*)(dsm + WS_BYTES + XS_BYTES);
    float*  Ssum = Crow + CROW_FLOATS;

    const int tid  = threadIdx.x;
    const int warp = tid >> 5;
    const int lane = tid & 31;
    const int g    = warp >> 3;           // output yrow 0..1
    const int px0  = (warp & 7) * 16;     // pixel block
    const int b    = blockIdx.y;
    const int y0   = blockIdx.x * 2;

    // ---- stage X once: 6 input rows, transpose [ci][px] -> [px][ci] ----
    for (int task = warp; task < 96; task += 16) {
        int s = task >> 4, q = task & 15;
        int gy = refl(y0 + s - 2);
        const float* base = x + ((size_t)b * CIN + q * 4) * HW + (size_t)gy * W_;
        #pragma unroll
        for (int k = 0; k < 5; k++) {
            int c = lane + 32 * k;
            if (c < 132) {
                int gc = refl(c - 2);
                float v0 = base[0 * HW + gc];
                float v1 = base[1 * HW + gc];
                float v2 = base[2 * HW + gc];
                float v3 = base[3 * HW + gc];
                uint32_t p0, p1;
                asm("cvt.rn.f16x2.f32 %0, %1, %2;" : "=r"(p0) : "f"(v1), "f"(v0));
                asm("cvt.rn.f16x2.f32 %0, %1, %2;" : "=r"(p1) : "f"(v3), "f"(v2));
                *(uint2*)(Xs + (size_t)s * XROW + (size_t)c * XPAD + q * 4) =
                    make_uint2(p0, p1);
            }
        }
    }
    __syncthreads();

    // ---- per staged-row column sums of x^2 ----
    for (int t = tid; t < 792; t += 512) {
        int s = t / 132, c = t - s * 132;
        const uint4* p = (const uint4*)(Xs + (size_t)s * XROW + (size_t)c * XPAD);
        float sacc = 0.f;
        #pragma unroll
        for (int i = 0; i < 8; i++) {
            uint4 u = p[i];
            const uint32_t uu[4] = {u.x, u.y, u.z, u.w};
            #pragma unroll
            for (int j = 0; j < 4; j++) {
                float2 f = __half22float2(*(const __half2*)&uu[j]);
                sacc = fmaf(f.x, f.x, fmaf(f.y, f.y, sacc));
            }
        }
        Crow[t] = sacc;
    }
    __syncthreads();

    // ---- 5-row window sums -> Ssum[out row][padded col] ----
    for (int t = tid; t < 264; t += 512) {
        int r = t / 132, c = t - r * 132;
        Ssum[t] = Crow[(r + 0) * 132 + c] + Crow[(r + 1) * 132 + c]
                + Crow[(r + 2) * 132 + c] + Crow[(r + 3) * 132 + c]
                + Crow[(r + 4) * 132 + c];
    }

    // ---- accumulators: [nt 0..7][4] ----
    float acc[8][4];
    #pragma unroll
    for (int nt = 0; nt < 8; nt++)
        #pragma unroll
        for (int i = 0; i < 4; i++) acc[nt][i] = 0.f;

    // ldmatrix lane mappings (verified in R5/R6)
    const int m_off = ((lane >> 3) & 1) * 8 + (lane & 7);      // A rows (0..15)
    const int k_off = (lane >> 4) * 8;                          // A k segment
    const int brow  = (lane & 7) + ((lane >> 4) << 3);          // B n row
    const int bk    = ((lane >> 3) & 1) * 8;                    // B k segment

    for (int kh = 0; kh < 5; kh++) {
        __syncthreads();   // previous kh's taps done reading Ws
        {
            const uint4* src = (const uint4*)(g_wh + (size_t)kh * 5 * 64 * WPAD);
            uint4* dst = (uint4*)Ws;
            for (int i = tid; i < 2880; i += 512) dst[i] = src[i];
        }
        __syncthreads();

        #pragma unroll
        for (int kw = 0; kw < 5; kw++) {
            const __half* Ab = Xs + (size_t)(g + kh) * XROW
                                  + (size_t)(px0 + kw) * XPAD;
            #pragma unroll
            for (int kt = 0; kt < 4; kt++) {
                uint32_t a[4];
                uint32_t ad = smem_u32(Ab + (size_t)m_off * XPAD + kt * 16 + k_off);
                asm volatile(
                    "ldmatrix.sync.aligned.m8n8.x4.shared.b16 {%0,%1,%2,%3}, [%4];"
                    : "=r"(a[0]), "=r"(a[1]), "=r"(a[2]), "=r"(a[3])
                    : "r"(ad));
                #pragma unroll
                for (int np = 0; np < 4; np++) {
                    uint32_t bb[4];
                    uint32_t bd = smem_u32(Ws + (size_t)(kw * 64 + np * 16 + brow) * WPAD
                                              + kt * 16 + bk);
                    asm volatile(
                        "ldmatrix.sync.aligned.m8n8.x4.shared.b16 {%0,%1,%2,%3}, [%4];"
                        : "=r"(bb[0]), "=r"(bb[1]), "=r"(bb[2]), "=r"(bb[3])
                        : "r"(bd));
                    asm volatile(
                        "mma.sync.aligned.m16n8k16.row.col.f32.f16.f16.f32 "
                        "{%0,%1,%2,%3}, {%4,%5,%6,%7}, {%8,%9}, {%0,%1,%2,%3};"
                        : "+f"(acc[2 * np][0]), "+f"(acc[2 * np][1]),
                          "+f"(acc[2 * np][2]), "+f"(acc[2 * np][3])
                        : "r"(a[0]), "r"(a[1]), "r"(a[2]), "r"(a[3]),
                          "r"(bb[0]), "r"(bb[1]));
                    asm volatile(
                        "mma.sync.aligned.m16n8k16.row.col.f32.f16.f16.f32 "
                        "{%0,%1,%2,%3}, {%4,%5,%6,%7}, {%8,%9}, {%0,%1,%2,%3};"
                        : "+f"(acc[2 * np + 1][0]), "+f"(acc[2 * np + 1][1]),
                          "+f"(acc[2 * np + 1][2]), "+f"(acc[2 * np + 1][3])
                        : "r"(a[0]), "r"(a[1]), "r"(a[2]), "r"(a[3]),
                          "r"(bb[2]), "r"(bb[3]));
                }
            }
        }
    }
    __syncthreads();   // all taps done; smem (except Ssum at end) reusable

    // ---- epilogue: cosine norm + smem transpose + coalesced store ----
    float inv[2];
    #pragma unroll
    for (int h = 0; h < 2; h++) {
        int p = px0 + (lane >> 2) + h * 8;     // output px
        const float* sp = Ssum + g * 132 + p;   // window p..p+4
        float s = sp[0] + sp[1] + sp[2] + sp[3] + sp[4];
        inv[h] = rsqrtf(s + 1e-8f);
    }

    // per-warp buf [64 cout][20 px-pad] at base of dsm (Ws/Xs dead; Ssum at tail safe)
    float* buf = (float*)dsm + warp * (64 * 20);   // 16*64*20*4 = 81920 B
    #pragma unroll
    for (int nt = 0; nt < 8; nt++)
        #pragma unroll
        for (int reg = 0; reg < 4; reg++) {
            int co  = nt * 8 + (lane & 3) * 2 + (reg & 1);
            int pxl = (lane >> 2) + (reg >> 1) * 8;
            buf[co * 20 + pxl] = acc[nt][reg] * inv[reg >> 1];
        }
    __syncwarp();

    const int y = y0 + g;
    #pragma unroll
    for (int it = 0; it < 8; it++) {
        int row = it * 8 + (lane >> 2);   // cout
        int seg = lane & 3;               // 4-px segment
        float4 v = *(const float4*)&buf[row * 20 + seg * 4];
        *(float4*)&g_ybuf[(((size_t)b * COUT + row) * H_ + y) * W_ + px0 + seg * 4] = v;
    }
}

// ---------------- kernel 3: depthwise 5x5 DoG (zero pad) ----------------
__global__ __launch_bounds__(512)
void dog_kernel(float* __restrict__ out) {
    __shared__ float Ts[20 * 132];
    __shared__ float sd[25];

    const int tid = threadIdx.x;
    const int bc  = blockIdx.x;
    const int y0  = blockIdx.y * 16;

    if (tid < 25) sd[tid] = g_dog[tid];

    const float* src = g_ybuf + (size_t)bc * HW;
    for (int idx = tid; idx < 20 * 132; idx += 512) {
        int rr = idx / 132;
        int c  = idx - rr * 132;
        int gy = y0 + rr - 2;
        int gx = c - 2;
        float v = 0.f;
        if (gy >= 0 && gy < H_ && gx >= 0 && gx < W_) v = src[gy * W_ + gx];
        Ts[idx] = v;
    }
    __syncthreads();

    const int row = tid >> 5;
    const int t4  = (tid & 31) * 4;
    float a[4] = {0.f, 0.f, 0.f, 0.f};

    #pragma unroll
    for (int u = 0; u < 5; u++) {
        const float* rp = &Ts[(row + u) * 132 + t4];
        float4 xa = *(const float4*)rp;
        float4 xc = *(const float4*)(rp + 4);
        float xv[8] = {xa.x, xa.y, xa.z, xa.w, xc.x, xc.y, xc.z, xc.w};
        #pragma unroll
        for (int v = 0; v < 5; v++) {
            float dv = sd[u * 5 + v];
            #pragma unroll
            for (int j = 0; j < 4; j++) a[j] = fmaf(dv, xv[v + j], a[j]);
        }
    }
    float4 o = make_float4(a[0], a[1], a[2], a[3]);
    *(float4*)&out[(size_t)bc * HW + (y0 + row) * W_ + t4] = o;
}

// ---------------- launch ----------------
extern "C" void kernel_launch(void* const* d_in, const int* in_sizes, int n_in,
                              void* d_out, int out_size) {
    const float* x = (const float*)d_in[0];
    const float* w = (const float*)d_in[1];
    float* out = (float*)d_out;

    static bool attr_set = false;
    if (!attr_set) {
        cudaFuncSetAttribute(main_mma_kernel,
                             cudaFuncAttributeMaxDynamicSharedMemorySize, DSMEM);
        attr_set = true;
    }

    prep_kernel<<<64, 128>>>(w);
    main_mma_kernel<<<dim3(64, 16), 512, DSMEM>>>(x);
    dog_kernel<<<dim3(1024, 8), 512>>>(out);
}

// round 8
// speedup vs baseline: 1.0653x; 1.0653x over previous
#include <cuda_runtime.h>
#include <cuda_fp16.h>
#include <cstdint>
#include <math.h>

// Problem constants
#define B_   16
#define CIN  64
#define COUT 64
#define H_   128
#define W_   128
#define HW   (H_*W_)          // 16384
#define NPIX (B_*COUT*HW)     // 16,777,216

#define XPAD 72               // halves per px row (144 B): ldmatrix rows 16B-aligned, conflict-free
#define WPAD 72
#define XROW (132 * XPAD)     // halves per staged input row

// ---------------- device scratch (static, no allocation) ----------------
__device__ __align__(16) __half g_wh[25 * 64 * WPAD];   // [khw][cout][WPAD]
__device__ float g_dog[25];
__device__ __align__(16) float g_ybuf[NPIX];

__device__ __forceinline__ int refl(int i) {
    if (i < 0) return -i;
    if (i > 127) return 254 - i;
    return i;
}

__device__ __forceinline__ uint32_t smem_u32(const void* p) {
    uint32_t a;
    asm("{ .reg .u64 t; cvta.to.shared.u64 t, %1; cvt.u32.u64 %0, t; }"
        : "=r"(a) : "l"(p));
    return a;
}

// ---------------- kernel 1: weight prep (one block per cout) ----------------
__global__ __launch_bounds__(128)
void prep_kernel(const float* __restrict__ w) {
    __shared__ float ws[1600];
    __shared__ float invn[25];
    const int tid = threadIdx.x;
    const int o = blockIdx.x;

    for (int i = tid; i < 1600; i += 128) ws[i] = w[o * 1600 + i];
    __syncthreads();
    if (tid < 25) {
        float s = 0.f;
        #pragma unroll 8
        for (int ci = 0; ci < CIN; ci++) {
            float v = ws[ci * 25 + tid];
            s += v * v;
        }
        invn[tid] = 1.f / fmaxf(sqrtf(s), 1e-12f);
    }
    __syncthreads();
    for (int i = tid; i < 1600; i += 128) {
        int khw = i >> 6, ci = i & 63;
        float v = fabsf(ws[ci * 25 + khw]) * invn[khw];
        g_wh[(size_t)(khw * 64 + o) * WPAD + ci] = __float2half(v);
    }
    if (o == 0 && tid < 25) {
        int u = tid / 5 - 2, v = tid % 5 - 2;
        float d2 = (float)(u * u + v * v);
        const float two_pi = 6.2831853071795864769f;
        const float ae = 1.f / (two_pi * 1.44f);   // sigma_e = 1.2
        const float ai = 1.f / (two_pi * 1.96f);   // sigma_i = 1.4
        float val = ae * expf(-d2 / (2.f * 1.44f)) - ai * expf(-d2 / (2.f * 1.96f));
        g_dog[tid] = val / (ae - ai);
    }
}

// ---------------- kernel 2: fp16 HMMA implicit-GEMM conv + cosine ----------------
// Grid (64, 16): CTA = 2 output y-rows x 128 px x 64 cout. 256 thr = 8 warps.
// Warp w: px0 = w*16; warp tile M32 = 2 y-rows x 16 px, N64 (mt = y-row).
// smem: Ws[5kw][64][WPAD] 46080 | Xs[6 rows][132 px][XPAD] 114048 | Crow[6*132] | Ssum[2*132]
#define WS_BYTES (5 * 64 * WPAD * 2)            // 46080
#define XS_BYTES (6 * 132 * XPAD * 2)           // 114048
#define CROW_FLOATS (6 * 132)
#define SSUM_FLOATS (2 * 132)
#define DSMEM (WS_BYTES + XS_BYTES + (CROW_FLOATS + SSUM_FLOATS) * 4)  // 164352

__global__ __launch_bounds__(256, 1)
void main_mma_kernel(const float* __restrict__ x) {
    extern __shared__ char dsm[];
    __half* Ws   = (__half*)dsm;
    __half* Xs   = (__half*)(dsm + WS_BYTES);
    float*  Crow = (float*)(dsm + WS_BYTES + XS_BYTES);
    float*  Ssum = Crow + CROW_FLOATS;

    const int tid  = threadIdx.x;
    const int warp = tid >> 5;
    const int lane = tid & 31;
    const int px0  = warp * 16;           // pixel block (8 warps x 16 px)
    const int b    = blockIdx.y;
    const int y0   = blockIdx.x * 2;

    // ---- stage X once: 6 input rows, transpose [ci][px] -> [px][ci] ----
    for (int task = warp; task < 96; task += 8) {
        int s = task >> 4, q = task & 15;
        int gy = refl(y0 + s - 2);
        const float* base = x + ((size_t)b * CIN + q * 4) * HW + (size_t)gy * W_;
        #pragma unroll
        for (int k = 0; k < 5; k++) {
            int c = lane + 32 * k;
            if (c < 132) {
                int gc = refl(c - 2);
                float v0 = base[0 * HW + gc];
                float v1 = base[1 * HW + gc];
                float v2 = base[2 * HW + gc];
                float v3 = base[3 * HW + gc];
                uint32_t p0, p1;
                asm("cvt.rn.f16x2.f32 %0, %1, %2;" : "=r"(p0) : "f"(v1), "f"(v0));
                asm("cvt.rn.f16x2.f32 %0, %1, %2;" : "=r"(p1) : "f"(v3), "f"(v2));
                *(uint2*)(Xs + (size_t)s * XROW + (size_t)c * XPAD + q * 4) =
                    make_uint2(p0, p1);
            }
        }
    }
    __syncthreads();

    // ---- per staged-row column sums of x^2 ----
    for (int t = tid; t < 792; t += 256) {
        int s = t / 132, c = t - s * 132;
        const uint4* p = (const uint4*)(Xs + (size_t)s * XROW + (size_t)c * XPAD);
        float sacc = 0.f;
        #pragma unroll
        for (int i = 0; i < 8; i++) {
            uint4 u = p[i];
            const uint32_t uu[4] = {u.x, u.y, u.z, u.w};
            #pragma unroll
            for (int j = 0; j < 4; j++) {
                float2 f = __half22float2(*(const __half2*)&uu[j]);
                sacc = fmaf(f.x, f.x, fmaf(f.y, f.y, sacc));
            }
        }
        Crow[t] = sacc;
    }
    __syncthreads();

    // ---- 5-row window sums -> Ssum[out row][padded col] ----
    for (int t = tid; t < 264; t += 256) {
        int r = t / 132, c = t - r * 132;
        Ssum[t] = Crow[(r + 0) * 132 + c] + Crow[(r + 1) * 132 + c]
                + Crow[(r + 2) * 132 + c] + Crow[(r + 3) * 132 + c]
                + Crow[(r + 4) * 132 + c];
    }

    // ---- accumulators: [mt = y-row][nt][4] ----
    float acc[2][8][4];
    #pragma unroll
    for (int mt = 0; mt < 2; mt++)
        #pragma unroll
        for (int nt = 0; nt < 8; nt++)
            #pragma unroll
            for (int i = 0; i < 4; i++) acc[mt][nt][i] = 0.f;

    // ldmatrix lane mappings (verified R5/R6)
    const int m_off = ((lane >> 3) & 1) * 8 + (lane & 7);      // A rows (px 0..15)
    const int k_off = (lane >> 4) * 8;                          // A k segment
    const int brow  = (lane & 7) + ((lane >> 4) << 3);          // B n row
    const int bk    = ((lane >> 3) & 1) * 8;                    // B k segment

    for (int kh = 0; kh < 5; kh++) {
        __syncthreads();   // previous kh's taps done reading Ws
        {
            const uint4* src = (const uint4*)(g_wh + (size_t)kh * 5 * 64 * WPAD);
            uint4* dst = (uint4*)Ws;
            for (int i = tid; i < 2880; i += 256) dst[i] = src[i];
        }
        __syncthreads();

        #pragma unroll
        for (int kw = 0; kw < 5; kw++) {
            // A fragments: mt = y-row (rows y0+mt), 16 px each
            uint32_t a[4][2][4];
            #pragma unroll
            for (int mt = 0; mt < 2; mt++) {
                const __half* Ab = Xs + (size_t)(mt + kh) * XROW
                                      + (size_t)(px0 + kw) * XPAD;
                #pragma unroll
                for (int kt = 0; kt < 4; kt++) {
                    uint32_t ad = smem_u32(Ab + (size_t)m_off * XPAD + kt * 16 + k_off);
                    asm volatile(
                        "ldmatrix.sync.aligned.m8n8.x4.shared.b16 {%0,%1,%2,%3}, [%4];"
                        : "=r"(a[kt][mt][0]), "=r"(a[kt][mt][1]),
                          "=r"(a[kt][mt][2]), "=r"(a[kt][mt][3])
                        : "r"(ad));
                }
            }
            #pragma unroll
            for (int np = 0; np < 4; np++) {
                #pragma unroll
                for (int kt = 0; kt < 4; kt++) {
                    uint32_t bb[4];
                    uint32_t bd = smem_u32(Ws + (size_t)(kw * 64 + np * 16 + brow) * WPAD
                                              + kt * 16 + bk);
                    asm volatile(
                        "ldmatrix.sync.aligned.m8n8.x4.shared.b16 {%0,%1,%2,%3}, [%4];"
                        : "=r"(bb[0]), "=r"(bb[1]), "=r"(bb[2]), "=r"(bb[3])
                        : "r"(bd));
                    #pragma unroll
                    for (int mt = 0; mt < 2; mt++) {
                        asm volatile(
                            "mma.sync.aligned.m16n8k16.row.col.f32.f16.f16.f32 "
                            "{%0,%1,%2,%3}, {%4,%5,%6,%7}, {%8,%9}, {%0,%1,%2,%3};"
                            : "+f"(acc[mt][2 * np][0]), "+f"(acc[mt][2 * np][1]),
                              "+f"(acc[mt][2 * np][2]), "+f"(acc[mt][2 * np][3])
                            : "r"(a[kt][mt][0]), "r"(a[kt][mt][1]),
                              "r"(a[kt][mt][2]), "r"(a[kt][mt][3]),
                              "r"(bb[0]), "r"(bb[1]));
                        asm volatile(
                            "mma.sync.aligned.m16n8k16.row.col.f32.f16.f16.f32 "
                            "{%0,%1,%2,%3}, {%4,%5,%6,%7}, {%8,%9}, {%0,%1,%2,%3};"
                            : "+f"(acc[mt][2 * np + 1][0]), "+f"(acc[mt][2 * np + 1][1]),
                              "+f"(acc[mt][2 * np + 1][2]), "+f"(acc[mt][2 * np + 1][3])
                            : "r"(a[kt][mt][0]), "r"(a[kt][mt][1]),
                              "r"(a[kt][mt][2]), "r"(a[kt][mt][3]),
                              "r"(bb[2]), "r"(bb[3]));
                    }
                }
            }
        }
    }
    __syncthreads();   // all taps done; smem (except Ssum at tail) reusable

    // ---- epilogue: cosine norm + smem transpose + coalesced store ----
    float inv[2][2];   // [mt][h]
    #pragma unroll
    for (int mt = 0; mt < 2; mt++)
        #pragma unroll
        for (int h = 0; h < 2; h++) {
            int p = px0 + (lane >> 2) + h * 8;      // output px
            const float* sp = Ssum + mt * 132 + p;   // window p..p+4
            float s = sp[0] + sp[1] + sp[2] + sp[3] + sp[4];
            inv[mt][h] = rsqrtf(s + 1e-8f);
        }

    // per-warp buf [2 rows][64 cout][20 px-pad] (8 warps * 10240 B = 81920 B at dsm base)
    float* buf = (float*)dsm + warp * (2 * 64 * 20);
    #pragma unroll
    for (int mt = 0; mt < 2; mt++)
        #pragma unroll
        for (int nt = 0; nt < 8; nt++)
            #pragma unroll
            for (int reg = 0; reg < 4; reg++) {
                int co  = nt * 8 + (lane & 3) * 2 + (reg & 1);
                int pxl = (lane >> 2) + (reg >> 1) * 8;
                buf[(mt * 64 + co) * 20 + pxl] = acc[mt][nt][reg] * inv[mt][reg >> 1];
            }
    __syncwarp();

    #pragma unroll
    for (int mt = 0; mt < 2; mt++) {
        const int y = y0 + mt;
        #pragma unroll
        for (int it = 0; it < 8; it++) {
            int row = it * 8 + (lane >> 2);   // cout
            int seg = lane & 3;               // 4-px segment
            float4 v = *(const float4*)&buf[(mt * 64 + row) * 20 + seg * 4];
            *(float4*)&g_ybuf[(((size_t)b * COUT + row) * H_ + y) * W_ + px0 + seg * 4] = v;
        }
    }
}

// ---------------- kernel 3: depthwise 5x5 DoG (zero pad) ----------------
__global__ __launch_bounds__(512)
void dog_kernel(float* __restrict__ out) {
    __shared__ float Ts[20 * 132];
    __shared__ float sd[25];

    const int tid = threadIdx.x;
    const int bc  = blockIdx.x;
    const int y0  = blockIdx.y * 16;

    if (tid < 25) sd[tid] = g_dog[tid];

    const float* src = g_ybuf + (size_t)bc * HW;
    for (int idx = tid; idx < 20 * 132; idx += 512) {
        int rr = idx / 132;
        int c  = idx - rr * 132;
        int gy = y0 + rr - 2;
        int gx = c - 2;
        float v = 0.f;
        if (gy >= 0 && gy < H_ && gx >= 0 && gx < W_) v = src[gy * W_ + gx];
        Ts[idx] = v;
    }
    __syncthreads();

    const int row = tid >> 5;
    const int t4  = (tid & 31) * 4;
    float a[4] = {0.f, 0.f, 0.f, 0.f};

    #pragma unroll
    for (int u = 0; u < 5; u++) {
        const float* rp = &Ts[(row + u) * 132 + t4];
        float4 xa = *(const float4*)rp;
        float4 xc = *(const float4*)(rp + 4);
        float xv[8] = {xa.x, xa.y, xa.z, xa.w, xc.x, xc.y, xc.z, xc.w};
        #pragma unroll
        for (int v = 0; v < 5; v++) {
            float dv = sd[u * 5 + v];
            #pragma unroll
            for (int j = 0; j < 4; j++) a[j] = fmaf(dv, xv[v + j], a[j]);
        }
    }
    float4 o = make_float4(a[0], a[1], a[2], a[3]);
    *(float4*)&out[(size_t)bc * HW + (y0 + row) * W_ + t4] = o;
}

// ---------------- launch ----------------
extern "C" void kernel_launch(void* const* d_in, const int* in_sizes, int n_in,
                              void* d_out, int out_size) {
    const float* x = (const float*)d_in[0];
    const float* w = (const float*)d_in[1];
    float* out = (float*)d_out;

    static bool attr_set = false;
    if (!attr_set) {
        cudaFuncSetAttribute(main_mma_kernel,
                             cudaFuncAttributeMaxDynamicSharedMemorySize, DSMEM);
        attr_set = true;
    }

    prep_kernel<<<64, 128>>>(w);
    main_mma_kernel<<<dim3(64, 16), 256, DSMEM>>>(x);
    dog_kernel<<<dim3(1024, 8), 512>>>(out);
}